// round 10
// baseline (speedup 1.0000x reference)
#include <cuda_runtime.h>
#include <cstdint>

#define T_ 256
#define B_ 64
#define M_ 512
#define N_ 1024
#define NB_REC 128
#define NBD 128         // arrivals per direction barrier (all blocks' halves)

// Scratch: G[dir*3+gate][t][b][n]  (gate order f,i,c)
__device__ float g_G[(size_t)6 * T_ * N_ * B_];
// h double buffer, k-pair-permuted + tf32-rounded: [buf][dir][b][kslot 1024]
__device__ float g_hP[2][2][B_ * N_];
// U packed in mma-fragment order as tf32 bit patterns:
// [dir][tile 128][kq 4][c 8][ks 4][rg 2][lane 32] uint4
__device__ uint4 g_Upk[1u << 21];
// per-step per-dir grid barrier counters (zeroed by k_init every launch)
__device__ unsigned g_bar[2 * T_];

struct PW { const float* p[6]; };
struct PU { const float* U[8]; const float* bia[8]; };

__device__ __forceinline__ uint32_t f2tf(float v) {
  uint32_t u; asm("cvt.rna.tf32.f32 %0, %1;" : "=r"(u) : "f"(v)); return u;
}
__device__ __forceinline__ void mma8(float* c, uint32_t a0, uint32_t a1,
                                     uint32_t a2, uint32_t a3,
                                     uint32_t b0, uint32_t b1) {
  asm volatile(
    "mma.sync.aligned.m16n8k8.row.col.f32.tf32.tf32.f32 "
    "{%0,%1,%2,%3},{%4,%5,%6,%7},{%8,%9},{%0,%1,%2,%3};\n"
    : "+f"(c[0]), "+f"(c[1]), "+f"(c[2]), "+f"(c[3])
    : "r"(a0), "r"(a1), "r"(a2), "r"(a3), "r"(b0), "r"(b1));
}
__device__ __forceinline__ void cpa16(uint32_t d, const void* s) {
  asm volatile("cp.async.cg.shared.global [%0], [%1], 16;" :: "r"(d), "l"(s));
}
__device__ __forceinline__ void barn(int id, int cnt) {
  asm volatile("bar.sync %0, %1;" :: "r"(id), "r"(cnt) : "memory");
}
__device__ __forceinline__ int kperm(int n) {        // pair (k, k+4) adjacent
  return (n & ~7) + ((n & 3) << 1) + ((n >> 2) & 1);
}
__device__ __forceinline__ float sigm_f(float x) {
  return __fdividef(1.f, 1.f + __expf(-x));
}
__device__ __forceinline__ float tanh_f(float x) {
  return 1.f - __fdividef(2.f, __expf(2.f * x) + 1.f);
}

__global__ void k_init(const float* __restrict__ hidden) {
  int i = blockIdx.x * blockDim.x + threadIdx.x;   // 65536 threads
  if (i < B_ * N_) {
    int b = i >> 10, n = i & 1023;
    float v = __uint_as_float(f2tf(hidden[i]));
    g_hP[0][0][b * N_ + kperm(n)] = v;
    g_hP[0][1][b * N_ + kperm(n)] = v;
  }
  if (i < 2 * T_) g_bar[i] = 0;
}

// Pack U into fragment order (one uint4 per thread).
// uint4 = (U_{2rg}[row,k], U_{2rg+1}[row,k], U_{2rg}[row,k+4], U_{2rg+1}[row,k+4])
__global__ void __launch_bounds__(256) k_pack(PU pu) {
  unsigned i = blockIdx.x * 256 + threadIdx.x;
  unsigned lane = i & 31, rg = (i >> 5) & 1, ks = (i >> 6) & 3,
           c = (i >> 8) & 7, kq = (i >> 11) & 3, tile = (i >> 13) & 127,
           dir = (i >> 20) & 1;
  int g4 = lane >> 2, tq = lane & 3;
  int row = tile * 8 + g4;
  int k = kq * 256 + c * 32 + ks * 8 + tq;
  const float* U0 = pu.U[dir * 4 + 2 * rg];
  const float* U1 = pu.U[dir * 4 + 2 * rg + 1];
  uint4 o;
  o.x = f2tf(U0[(size_t)row * N_ + k]);
  o.y = f2tf(U1[(size_t)row * N_ + k]);
  o.z = f2tf(U0[(size_t)row * N_ + k + 4]);
  o.w = f2tf(U1[(size_t)row * N_ + k + 4]);
  g_Upk[i] = o;
}

// ---------------- Phase 1: G[dg][t][b][n] = sum_m x[t_src,b,m] * W[m,n] ----
__device__ __forceinline__ float4 cvt4(float4 v) {
  float4 r;
  r.x = __uint_as_float(f2tf(v.x)); r.y = __uint_as_float(f2tf(v.y));
  r.z = __uint_as_float(f2tf(v.z)); r.w = __uint_as_float(f2tf(v.w));
  return r;
}

__global__ void __launch_bounds__(256) k_gemm_xw(const float* __restrict__ x, PW pw) {
  __shared__ __align__(16) float As[64][36];
  __shared__ __align__(16) float Bs[32][136];
  int tid = threadIdx.x;
  int wid = tid >> 5, lane = tid & 31;
  int g4 = lane >> 2, tq = lane & 3;
  int wm = wid & 1, wn = wid >> 1;
  int n0 = blockIdx.x * 128;
  int t = blockIdx.y;
  int dg = blockIdx.z;
  int dir = dg / 3;
  int t_src = dir ? (T_ - 1 - t) : t;
  const float* W = pw.p[dg];
  const float* xt = x + (size_t)t_src * (B_ * M_);

  float acc[2][4][4];
  #pragma unroll
  for (int a = 0; a < 2; a++)
    #pragma unroll
    for (int b = 0; b < 4; b++)
      #pragma unroll
      for (int cc = 0; cc < 4; cc++) acc[a][b][cc] = 0.f;

  for (int k0 = 0; k0 < M_; k0 += 32) {
    #pragma unroll
    for (int j = 0; j < 2; j++) {
      int i = tid + j * 256;
      int bb = i >> 3, kq = (i & 7) << 2;
      *(float4*)&As[bb][kq] = cvt4(*(const float4*)(xt + bb * M_ + k0 + kq));
    }
    #pragma unroll
    for (int j = 0; j < 4; j++) {
      int i = tid + j * 256;
      int kk = i >> 5, nq = (i & 31) << 2;
      *(float4*)&Bs[kk][nq] = cvt4(*(const float4*)(W + (size_t)(k0 + kk) * N_ + n0 + nq));
    }
    __syncthreads();
    #pragma unroll
    for (int ks = 0; ks < 32; ks += 8) {
      uint32_t af[2][4];
      #pragma unroll
      for (int mt = 0; mt < 2; mt++) {
        int r = wm * 32 + mt * 16 + g4;
        af[mt][0] = __float_as_uint(As[r][ks + tq]);
        af[mt][1] = __float_as_uint(As[r + 8][ks + tq]);
        af[mt][2] = __float_as_uint(As[r][ks + tq + 4]);
        af[mt][3] = __float_as_uint(As[r + 8][ks + tq + 4]);
      }
      #pragma unroll
      for (int nt = 0; nt < 4; nt++) {
        int ccol = wn * 32 + nt * 8 + g4;
        uint32_t b0 = __float_as_uint(Bs[ks + tq][ccol]);
        uint32_t b1 = __float_as_uint(Bs[ks + tq + 4][ccol]);
        #pragma unroll
        for (int mt = 0; mt < 2; mt++)
          mma8(acc[mt][nt], af[mt][0], af[mt][1], af[mt][2], af[mt][3], b0, b1);
      }
    }
    __syncthreads();
  }
  size_t gb = (size_t)(dg * T_ + t) * (N_ * B_);
  #pragma unroll
  for (int mt = 0; mt < 2; mt++) {
    int brow = wm * 32 + mt * 16 + g4;
    #pragma unroll
    for (int nt = 0; nt < 4; nt++) {
      int nc = n0 + wn * 32 + nt * 8 + 2 * tq;
      *(float2*)&g_G[gb + (size_t)brow * N_ + nc] =
          make_float2(acc[mt][nt][0], acc[mt][nt][1]);
      *(float2*)&g_G[gb + (size_t)(brow + 8) * N_ + nc] =
          make_float2(acc[mt][nt][2], acc[mt][nt][3]);
    }
  }
}

// ---------------- Phase 2: persistent recurrent kernel ---------------------
// 512 thr = 2 INDEPENDENT halves of 256; half h runs direction h on tile
// blockIdx.x (8 n-rows). Within a half: 4 warp-pairs, pair kq owns k-slice
// [kq*256, +256) in 8 chunks of 32, staged in a private double buffer.
// Warp rg of a pair: gates {2rg, 2rg+1} (16 U-rows = one m16 tile).
// All sync via named barriers: pair id 1+p (64 thr), half id 9+h (256 thr).
#define BUFW 2560                  // 64 b * 40 words per chunk buffer
#define PAIRW 5120                 // 2 buffers per pair
#define SMEM_BYTES (8 * PAIRW * 4) // 163840
// zs overlaid on each pair's own region after drain: [r 32][cl 66]
#define ZS(p, r, cl) ((p) * PAIRW + (r) * 66 + (cl))

__global__ void __launch_bounds__(512) k_recur(PU pu, float* __restrict__ out) {
  extern __shared__ float sm[];
  uint32_t smb = (uint32_t)__cvta_generic_to_shared(sm);
  int tid = threadIdx.x, lane = tid & 31;
  int h = tid >> 8;                       // = direction
  int ht = tid & 255;                     // half-local tid
  int wid_h = ht >> 5;
  int g4 = lane >> 2, tq = lane & 3;
  int rg = wid_h & 1, kq = wid_h >> 1;
  int pt = rg * 32 + lane;                // pair-local tid 0..63
  int p = h * 4 + kq;                     // pair region index 0..7
  int bar_pair = 1 + p;
  int bar_half = 9 + h;
  int dir = h;
  int bl = blockIdx.x;                    // tile 0..127 (8 n-rows)
  int rn = bl << 3;

  const uint4* upk = g_Upk + ((((size_t)dir * 128 + bl) * 4 + kq) * 2048)
                     + rg * 32 + lane;
  uint32_t pair_smb = smb + p * PAIRW * 4;

  // elementwise ownership (within half): b = ht>>2, n = rn + nn, nn+1
  int b_e = ht >> 2;
  int nn = (ht & 3) << 1;

  float bia[4][2];
  #pragma unroll
  for (int g = 0; g < 4; g++) {
    bia[g][0] = pu.bia[dir * 4 + g][rn + nn];
    bia[g][1] = pu.bia[dir * 4 + g][rn + nn + 1];
  }
  const float* Gb0 = g_G + (size_t)(dir * 3 + 0) * T_ * N_ * B_;
  const float* Gb1 = g_G + (size_t)(dir * 3 + 1) * T_ * N_ * B_;
  const float* Gb2 = g_G + (size_t)(dir * 3 + 2) * T_ * N_ * B_;
  int hslot0 = kperm(rn + nn), hslot1 = kperm(rn + nn + 1);
  unsigned* barp = &g_bar[dir * T_];

  float creg[2] = {0.f, 0.f};

  for (int s = 0; s < T_; ++s) {
    const float* hsrc = g_hP[s & 1][dir];
    const float* hkq = hsrc + kq * 256;

    // stage chunks 0,1 into bufs 0,1 (pair-private)
    #pragma unroll
    for (int c0 = 0; c0 < 2; c0++) {
      #pragma unroll
      for (int j = 0; j < 8; j++) {
        int unit = pt + j * 64;
        int b = unit >> 3, seg = unit & 7;
        cpa16(pair_smb + (c0 * BUFW + b * 40 + seg * 4) * 4,
              hkq + b * N_ + c0 * 32 + seg * 4);
      }
      asm volatile("cp.async.commit_group;");
    }

    // prefetch this step's G (coalesced float2, [t][b][n] layout)
    size_t goff = ((size_t)s * B_ + b_e) * N_ + rn + nn;
    float2 gq0 = __ldg((const float2*)(Gb0 + goff));
    float2 gq1 = __ldg((const float2*)(Gb1 + goff));
    float2 gq2 = __ldg((const float2*)(Gb2 + goff));

    float acc[8][4];
    #pragma unroll
    for (int nt = 0; nt < 8; nt++)
      #pragma unroll
      for (int cc = 0; cc < 4; cc++) acc[nt][cc] = 0.f;

    // 8 chunks x 4 k-steps; one m16 A-tile per warp per k-step
    #pragma unroll 1
    for (int c = 0; c < 8; ++c) {
      if (c < 7) asm volatile("cp.async.wait_group 1;");
      else       asm volatile("cp.async.wait_group 0;");
      barn(bar_pair, 64);                // chunk c visible to both warps

      const float* bb = sm + p * PAIRW + (c & 1) * BUFW + 2 * tq;
      const uint4* up = upk + c * 256;
      #pragma unroll
      for (int ks = 0; ks < 4; ++ks) {
        uint4 A = __ldg(up + ks * 64);
        #pragma unroll
        for (int nt = 0; nt < 8; ++nt) {
          uint2 Bv = *(const uint2*)(bb + (nt * 8 + g4) * 40 + ks * 8);
          mma8(acc[nt], A.x, A.y, A.z, A.w, Bv.x, Bv.y);
        }
      }
      if (c < 6) {
        barn(bar_pair, 64);              // both warps done with buf c&1
        int cn = c + 2;
        #pragma unroll
        for (int j = 0; j < 8; j++) {
          int unit = pt + j * 64;
          int b = unit >> 3, seg = unit & 7;
          cpa16(pair_smb + ((c & 1) * BUFW + b * 40 + seg * 4) * 4,
                hkq + b * N_ + cn * 32 + seg * 4);
        }
        asm volatile("cp.async.commit_group;");
      }
    }

    barn(bar_pair, 64);   // partner drained buf1 -> pair region reusable as zs

    // write k-partials into own pair region: zs[p][gate*8 + n][b]
    {
      int r0 = (2 * rg) * 8 + g4;
      int r1 = (2 * rg + 1) * 8 + g4;
      #pragma unroll
      for (int nt = 0; nt < 8; nt++) {
        int cl = nt * 8 + 2 * tq;
        *(float2*)&sm[ZS(p, r0, cl)] = make_float2(acc[nt][0], acc[nt][1]);
        *(float2*)&sm[ZS(p, r1, cl)] = make_float2(acc[nt][2], acc[nt][3]);
      }
    }
    barn(bar_half, 256);

    // elementwise LSTM cell (2 consecutive n per thread, one b)
    float z[4][2];
    #pragma unroll
    for (int g = 0; g < 4; g++) {
      #pragma unroll
      for (int e = 0; e < 2; e++) {
        float zz = bia[g][e];
        #pragma unroll
        for (int q = 0; q < 4; q++)
          zz += sm[ZS(h * 4 + q, g * 8 + nn + e, b_e)];
        z[g][e] = zz;
      }
    }
    float* hdst = g_hP[(s + 1) & 1][dir];
    int t_out = dir ? (T_ - 1 - s) : s;
    float2 ho;
    #pragma unroll
    for (int e = 0; e < 2; e++) {
      float gf = e ? gq0.y : gq0.x;
      float gi = e ? gq1.y : gq1.x;
      float gc = e ? gq2.y : gq2.x;
      float zf = z[0][e] + gf, zi = z[1][e] + gi;
      float zc = z[2][e] + gc, zo = z[3][e] + gf;   // o reuses gf (ref bug)
      float f  = sigm_f(zf);
      float ig = sigm_f(zi);
      float o  = sigm_f(zo);
      float cn = f * creg[e] + ig * tanh_f(zc);
      creg[e] = cn;
      float hh = o * tanh_f(cn);
      ((float*)&ho)[e] = hh;
      __stcg(hdst + b_e * N_ + (e ? hslot1 : hslot0), __uint_as_float(f2tf(hh)));
    }
    *(float2*)(out + ((size_t)t_out * B_ + b_e) * (2 * N_) +
               (size_t)dir * N_ + rn + nn) = ho;

    // per-direction grid barrier, half-scoped (other half keeps computing)
    if (s < T_ - 1) {
      barn(bar_half, 256);   // all half stores + zs reads done
      if (ht == 0) {
        unsigned v;
        asm volatile("atom.add.acq_rel.gpu.global.u32 %0, [%1], 1;"
                     : "=r"(v) : "l"(&barp[s]) : "memory");
        if (v + 1u < NBD) {
          unsigned w;
          do {
            asm volatile("ld.acquire.gpu.global.u32 %0, [%1];"
                         : "=r"(w) : "l"(&barp[s]) : "memory");
            if (w >= NBD) break;
            __nanosleep(32);
          } while (true);
        }
      }
      barn(bar_half, 256);   // acquire ordering propagates half-wide
    }
  }
}

extern "C" void kernel_launch(void* const* d_in, const int* in_sizes, int n_in,
                              void* d_out, int out_size) {
  const float* x      = (const float*)d_in[0];
  const float* hidden = (const float*)d_in[1];
  PW pw;
  pw.p[0] = (const float*)d_in[2];   // Wf1
  pw.p[1] = (const float*)d_in[3];   // Wi1
  pw.p[2] = (const float*)d_in[4];   // Wc1
  pw.p[3] = (const float*)d_in[13];  // Wf2
  pw.p[4] = (const float*)d_in[14];  // Wi2
  pw.p[5] = (const float*)d_in[15];  // Wc2

  PU pu;  // gate order f,i,c,o
  pu.U[0] = (const float*)d_in[5];   // Uf1
  pu.U[1] = (const float*)d_in[6];   // Ui1
  pu.U[2] = (const float*)d_in[8];   // Uc1
  pu.U[3] = (const float*)d_in[7];   // Uo1
  pu.U[4] = (const float*)d_in[16];  // Uf2
  pu.U[5] = (const float*)d_in[17];  // Ui2
  pu.U[6] = (const float*)d_in[19];  // Uc2
  pu.U[7] = (const float*)d_in[18];  // Uo2
  pu.bia[0] = (const float*)d_in[9];   // bf1
  pu.bia[1] = (const float*)d_in[10];  // bi1
  pu.bia[2] = (const float*)d_in[12];  // bc1
  pu.bia[3] = (const float*)d_in[11];  // bo1
  pu.bia[4] = (const float*)d_in[20];  // bf2
  pu.bia[5] = (const float*)d_in[21];  // bi2
  pu.bia[6] = (const float*)d_in[23];  // bc2
  pu.bia[7] = (const float*)d_in[22];  // bo2

  static int smem_set = 0;
  if (!smem_set) {
    cudaFuncSetAttribute(k_recur, cudaFuncAttributeMaxDynamicSharedMemorySize,
                         SMEM_BYTES);
    smem_set = 1;
  }

  k_init<<<256, 256>>>(hidden);
  k_pack<<<8192, 256>>>(pu);
  k_gemm_xw<<<dim3(8, 256, 6), 256>>>(x, pw);
  k_recur<<<NB_REC, 512, SMEM_BYTES>>>(pu, (float*)d_out);
}